// round 12
// baseline (speedup 1.0000x reference)
#include <cuda_runtime.h>
#include <cuda_fp16.h>
#include <cstdint>

#define B_   8
#define C_   512
#define S_   2048
#define L_   8921
#define LPAD 8960
#define NLT  70

// ---------------- device scratch ----------------
__device__ __align__(16) __half g_encB[B_][C_][S_];   // [b][c][s]
__device__ __align__(16) __half g_encT[B_][S_][C_];   // [b][s][c]
__device__ __align__(16) __half g_wB[LPAD][C_];
__device__ __align__(16) __half g_P[B_][LPAD][S_];    // exp(scores)
__device__ float g_Zinv[B_][LPAD];

// ---------------- helpers ----------------
__device__ __forceinline__ uint32_t smem_u32(const void* p) {
    uint32_t a;
    asm("{ .reg .u64 t; cvta.to.shared.u64 t, %1; cvt.u32.u64 %0, t; }" : "=r"(a) : "l"(p));
    return a;
}
#define CPA(dst, src) \
    asm volatile("cp.async.cg.shared.global [%0], [%1], 16;" :: "r"(dst), "l"(src))
#define CPC() asm volatile("cp.async.commit_group;" ::: "memory")
#define CPW(n) asm volatile("cp.async.wait_group %0;" :: "n"(n) : "memory")

__device__ __forceinline__ void ldsm4(uint32_t* r, uint32_t addr) {
    asm volatile("ldmatrix.sync.aligned.m8n8.x4.shared.b16 {%0,%1,%2,%3}, [%4];"
        : "=r"(r[0]), "=r"(r[1]), "=r"(r[2]), "=r"(r[3]) : "r"(addr));
}
// fp32-accumulate HMMA (K2)
__device__ __forceinline__ void mma16816(float* d, const uint32_t* a, const uint32_t* b) {
    asm volatile("mma.sync.aligned.m16n8k16.row.col.f32.f16.f16.f32 "
        "{%0,%1,%2,%3}, {%4,%5,%6,%7}, {%8,%9}, {%0,%1,%2,%3};"
        : "+f"(d[0]), "+f"(d[1]), "+f"(d[2]), "+f"(d[3])
        : "r"(a[0]), "r"(a[1]), "r"(a[2]), "r"(a[3]), "r"(b[0]), "r"(b[1]));
}
// fp16-accumulate HMMA (K1 experiment): D = {c0c1, c2c3} packed half2
__device__ __forceinline__ void mma16816h(uint32_t* d, const uint32_t* a, const uint32_t* b) {
    asm volatile("mma.sync.aligned.m16n8k16.row.col.f16.f16.f16.f16 "
        "{%0,%1}, {%2,%3,%4,%5}, {%6,%7}, {%0,%1};"
        : "+r"(d[0]), "+r"(d[1])
        : "r"(a[0]), "r"(a[1]), "r"(a[2]), "r"(a[3]), "r"(b[0]), "r"(b[1]));
}

// ---------------- prep kernels ----------------
__global__ void prep_enc(const float* __restrict__ enc) {
    __shared__ float t[32][33];
    int b = blockIdx.z, c0 = blockIdx.x * 32, s0 = blockIdx.y * 32;
    int tx = threadIdx.x & 31, ty = threadIdx.x >> 5;   // 256 threads: 32x8
    #pragma unroll
    for (int r = 0; r < 4; r++) {
        int c = c0 + ty + 8 * r;
        float v = enc[((size_t)b * C_ + c) * S_ + s0 + tx];
        t[ty + 8 * r][tx] = v;
        g_encB[b][c][s0 + tx] = __float2half(v);
    }
    __syncthreads();
    #pragma unroll
    for (int r = 0; r < 4; r++) {
        int s = s0 + ty + 8 * r;
        g_encT[b][s][c0 + tx] = __float2half(t[tx][ty + 8 * r]);
    }
}
__global__ void prep_w(const float* __restrict__ W) {
    int i = blockIdx.x * blockDim.x + threadIdx.x;
    int l = i >> 9, c = i & (C_ - 1);
    g_wB[l][c] = __float2half(l < L_ ? W[(size_t)l * C_ + c] : 0.0f);
}
__global__ void out_init(const float* __restrict__ b_cls, float* __restrict__ out) {
    int i = blockIdx.x * blockDim.x + threadIdx.x;
    if (i < B_ * L_) out[i] = b_cls[i % L_];
}

// ---------------- K1: scores + exp + Z (fp16-accum experiment) ----------------
// CTA: 128 labels x 128 s per chunk, K=C=512. 512 threads, 16 warps of 32x32.
// fp16 accumulation within each 64-k group, promoted to fp32 once per group.
#define K1_SB    (512 + 131072)
#define K1_SMEM  (512 + 131072 + 2 * 16384)

__global__ __launch_bounds__(512, 1) void k1_scores() {
    extern __shared__ char sm[];
    float* zs = (float*)sm;
    char* sA = sm + 512;
    const uint32_t sAu = smem_u32(sA), sBu = smem_u32(sm + K1_SB);
    const int tid = threadIdx.x, lane = tid & 31, wid = tid >> 5;
    const int wm = (wid >> 2) * 32, wn = (wid & 3) * 32;
    const int b = blockIdx.y, l0 = blockIdx.x * 128;

    if (tid < 128) zs[tid] = 0.f;

    // stage A: 128x512 -> 8 subtiles [128][64], 16B-XOR swizzled
    #pragma unroll
    for (int j = 0; j < 16; j++) {
        int lin = j * 512 + tid;
        int row = lin >> 6, seg = lin & 63;
        uint4 v = *(const uint4*)&g_wB[l0 + row][seg * 8];
        *(uint4*)(sA + (seg >> 3) * 16384 + row * 128 +
                  (((seg & 7) * 16) ^ ((row & 7) << 4))) = v;
    }
    __syncthreads();

    const int swz   = (lane & 7) << 4;
    const int arow  = lane & 15;                         // A: + wm + mt*16
    const int acolb = (lane >> 4) << 4;                  // A: + k0*2
    const int brow  = (lane & 7) + ((lane >> 4) << 3);   // B: + wn + ng*16
    const int bcolb = ((lane >> 3) & 1) << 4;            // B: + k0*2

    // staging: chunk = 128 s-rows x 64 k fp16 = 16KB; 4 threads/row, 2 x 16B each
    const int sbrow = tid >> 2;
    const int sbc0  = (tid & 3) << 1;

    float acc[2][4][4];      // fp32 running scores
    uint32_t h16[2][4][2];   // fp16 group accumulators
    float zr[2][2];
    #pragma unroll
    for (int mt = 0; mt < 2; mt++) { zr[mt][0] = 0.f; zr[mt][1] = 0.f; }

    // prologue: stage chunk 0 into buf 0
    #pragma unroll
    for (int q = 0; q < 2; q++) {
        int c16 = sbc0 + q;
        CPA(sBu + sbrow * 128 + ((c16 * 16) ^ ((sbrow & 7) << 4)),
            (const char*)&g_encT[b][sbrow][c16 * 8]);
    }
    CPC();

    #pragma unroll 1
    for (int it = 0; it < 128; it++) {                 // 16 s-chunks x 8 k-chunks
        const int n = it >> 3, kk = it & 7;
        const uint32_t bufo = (uint32_t)(it & 1) * 16384u;

        if (kk == 0) {
            #pragma unroll
            for (int mt = 0; mt < 2; mt++)
                #pragma unroll
                for (int nt = 0; nt < 4; nt++)
                    acc[mt][nt][0] = acc[mt][nt][1] = acc[mt][nt][2] = acc[mt][nt][3] = 0.f;
        }
        #pragma unroll
        for (int mt = 0; mt < 2; mt++)
            #pragma unroll
            for (int nt = 0; nt < 4; nt++) { h16[mt][nt][0] = 0u; h16[mt][nt][1] = 0u; }

        if (it < 127) {   // stage chunk it+1 into the other buffer
            const int n2 = (it + 1) >> 3, k2 = (it + 1) & 7;
            const uint32_t bo2 = (uint32_t)((it + 1) & 1) * 16384u;
            #pragma unroll
            for (int q = 0; q < 2; q++) {
                int c16 = sbc0 + q;
                CPA(sBu + bo2 + sbrow * 128 + ((c16 * 16) ^ ((sbrow & 7) << 4)),
                    (const char*)&g_encT[b][n2 * 128 + sbrow][k2 * 64 + c16 * 8]);
            }
            CPC();
            CPW(1);
        } else {
            CPW(0);
        }
        __syncthreads();

        const uint32_t aB = sAu + kk * 16384;
        #pragma unroll
        for (int ks = 0; ks < 4; ks++) {
            const int k0b = ks * 32;
            uint32_t a[2][4], bfr[2][4];
            #pragma unroll
            for (int mt = 0; mt < 2; mt++)
                ldsm4(a[mt], aB + (wm + mt * 16 + arow) * 128 + ((k0b + acolb) ^ swz));
            #pragma unroll
            for (int ng = 0; ng < 2; ng++)
                ldsm4(bfr[ng], sBu + bufo + (wn + ng * 16 + brow) * 128 + ((k0b + bcolb) ^ swz));
            #pragma unroll
            for (int mt = 0; mt < 2; mt++)
                #pragma unroll
                for (int ng = 0; ng < 2; ng++) {
                    mma16816h(h16[mt][2 * ng],     a[mt], &bfr[ng][0]);
                    mma16816h(h16[mt][2 * ng + 1], a[mt], &bfr[ng][2]);
                }
        }
        __syncthreads();   // all warps done with this buffer before re-stage

        // promote fp16 group accumulators into fp32 (once per 64-k group)
        #pragma unroll
        for (int mt = 0; mt < 2; mt++)
            #pragma unroll
            for (int nt = 0; nt < 4; nt++) {
                float2 lo = __half22float2(*(__half2*)&h16[mt][nt][0]);
                float2 hi = __half22float2(*(__half2*)&h16[mt][nt][1]);
                acc[mt][nt][0] += lo.x; acc[mt][nt][1] += lo.y;
                acc[mt][nt][2] += hi.x; acc[mt][nt][3] += hi.y;
            }

        if (kk == 7) {     // epilogue: exp, store P, accumulate Z
            const int sg = n * 128 + wn;
            #pragma unroll
            for (int mt = 0; mt < 2; mt++) {
                const int r0 = l0 + wm + mt * 16 + (lane >> 2);
                #pragma unroll
                for (int nt = 0; nt < 4; nt++) {
                    const int sc = sg + nt * 8 + ((lane & 3) << 1);
                    float e0 = __expf(acc[mt][nt][0]);
                    float e1 = __expf(acc[mt][nt][1]);
                    float e2 = __expf(acc[mt][nt][2]);
                    float e3 = __expf(acc[mt][nt][3]);
                    zr[mt][0] += e0 + e1;
                    zr[mt][1] += e2 + e3;
                    *(__half2*)&g_P[b][r0][sc]     = __floats2half2_rn(e0, e1);
                    *(__half2*)&g_P[b][r0 + 8][sc] = __floats2half2_rn(e2, e3);
                }
            }
        }
    }

    #pragma unroll
    for (int mt = 0; mt < 2; mt++) {
        atomicAdd(&zs[wm + mt * 16 + (lane >> 2)],     zr[mt][0]);
        atomicAdd(&zs[wm + mt * 16 + (lane >> 2) + 8], zr[mt][1]);
    }
    __syncthreads();
    if (tid < 128) g_Zinv[b][l0 + tid] = 1.0f / zs[tid];
}

// ---------------- K2: context + classifier (R9-exact, fp32 accum) ----------------
#define K2_SMEM (512 + 2 * 16384 + 2 * 32768)

__global__ __launch_bounds__(512, 1) void k2_context(const float* __restrict__ W_cls,
                                                     float* __restrict__ out) {
    extern __shared__ char sm[];
    float* red = (float*)sm;
    char* sA = sm + 512;
    char* sB = sm + 512 + 32768;
    const uint32_t sAu = smem_u32(sA), sBu = smem_u32(sB);
    const int tid = threadIdx.x, lane = tid & 31, wid = tid >> 5;
    const int wm = (wid >> 2) * 32, wn = (wid & 3) * 64;
    const int b = blockIdx.z, l0 = blockIdx.x * 128, c0 = blockIdx.y * 256;

    if (tid < 128) red[tid] = 0.f;

    const int swz   = (lane & 7) << 4;
    const int arow  = lane & 15;
    const int acolb = (lane >> 4) << 4;
    const int brow  = (lane & 7) + ((lane >> 4) << 3);
    const int bcolb = ((lane >> 3) & 1) << 4;

    float acc[2][8][4];
    #pragma unroll
    for (int mt = 0; mt < 2; mt++)
        #pragma unroll
        for (int nt = 0; nt < 8; nt++)
            acc[mt][nt][0] = acc[mt][nt][1] = acc[mt][nt][2] = acc[mt][nt][3] = 0.f;

    // prologue stage it=0
    #pragma unroll
    for (int j = 0; j < 2; j++) {
        int lin = j * 512 + tid;
        int row = lin >> 3, c16 = lin & 7;
        CPA(sAu + row * 128 + ((c16 * 16) ^ ((row & 7) << 4)),
            (const char*)&g_P[b][l0 + row][c16 * 8]);
    }
    #pragma unroll
    for (int j = 0; j < 4; j++) {
        int lin = j * 512 + tid;
        int row = lin >> 3, c16 = lin & 7;
        CPA(sBu + row * 128 + ((c16 * 16) ^ ((row & 7) << 4)),
            (const char*)&g_encB[b][c0 + row][c16 * 8]);
    }
    CPC();

    #pragma unroll 1
    for (int it = 0; it < 32; it++) {
        const uint32_t aBuf = (uint32_t)(it & 1) * 16384u;
        const uint32_t bBuf = (uint32_t)(it & 1) * 32768u;

        if (it < 31) {
            const int s2 = (it + 1) * 64;
            const uint32_t a2 = (uint32_t)((it + 1) & 1) * 16384u;
            const uint32_t b2 = (uint32_t)((it + 1) & 1) * 32768u;
            #pragma unroll
            for (int j = 0; j < 2; j++) {
                int lin = j * 512 + tid;
                int row = lin >> 3, c16 = lin & 7;
                CPA(sAu + a2 + row * 128 + ((c16 * 16) ^ ((row & 7) << 4)),
                    (const char*)&g_P[b][l0 + row][s2 + c16 * 8]);
            }
            #pragma unroll
            for (int j = 0; j < 4; j++) {
                int lin = j * 512 + tid;
                int row = lin >> 3, c16 = lin & 7;
                CPA(sBu + b2 + row * 128 + ((c16 * 16) ^ ((row & 7) << 4)),
                    (const char*)&g_encB[b][c0 + row][s2 + c16 * 8]);
            }
            CPC();
            CPW(1);
        } else {
            CPW(0);
        }
        __syncthreads();

        #pragma unroll
        for (int ks = 0; ks < 4; ks++) {
            const int k0b = ks * 32;
            uint32_t a[2][4], bfr[4][4];
            #pragma unroll
            for (int mt = 0; mt < 2; mt++)
                ldsm4(a[mt], sAu + aBuf + (wm + mt * 16 + arow) * 128 + ((k0b + acolb) ^ swz));
            #pragma unroll
            for (int ng = 0; ng < 4; ng++)
                ldsm4(bfr[ng], sBu + bBuf + (wn + ng * 16 + brow) * 128 + ((k0b + bcolb) ^ swz));
            #pragma unroll
            for (int mt = 0; mt < 2; mt++)
                #pragma unroll
                for (int ng = 0; ng < 4; ng++) {
                    mma16816(acc[mt][2 * ng],     a[mt], &bfr[ng][0]);
                    mma16816(acc[mt][2 * ng + 1], a[mt], &bfr[ng][2]);
                }
        }
        __syncthreads();
    }

    // epilogue: diagonal classifier dot + CTA reduce + global atomic
    #pragma unroll
    for (int mt = 0; mt < 2; mt++) {
        const int lloc = wm + mt * 16 + (lane >> 2);
        const int gl0 = l0 + lloc, gl1 = gl0 + 8;
        float v0 = 0.f, v1 = 0.f;
        #pragma unroll
        for (int nt = 0; nt < 8; nt++) {
            const int c = c0 + wn + nt * 8 + ((lane & 3) << 1);
            if (gl0 < L_) {
                const float* w = &W_cls[(size_t)gl0 * C_ + c];
                v0 += acc[mt][nt][0] * w[0] + acc[mt][nt][1] * w[1];
            }
            if (gl1 < L_) {
                const float* w = &W_cls[(size_t)gl1 * C_ + c];
                v1 += acc[mt][nt][2] * w[0] + acc[mt][nt][3] * w[1];
            }
        }
        atomicAdd(&red[lloc],     v0);
        atomicAdd(&red[lloc + 8], v1);
    }
    __syncthreads();
    if (tid < 128) {
        const int gl = l0 + tid;
        if (gl < L_)
            atomicAdd(&out[(size_t)b * L_ + gl], red[tid] * g_Zinv[b][gl]);
    }
}

// ---------------- launcher ----------------
extern "C" void kernel_launch(void* const* d_in, const int* in_sizes, int n_in,
                              void* d_out, int out_size) {
    const float* encoded = (const float*)d_in[0];
    const float* W_attn  = (const float*)d_in[1];
    // d_in[2] = b_attn: constant along the softmax axis -> no effect on output
    const float* W_cls   = (const float*)d_in[3];
    const float* b_cls   = (const float*)d_in[4];
    float* out = (float*)d_out;

    cudaFuncSetAttribute(k1_scores,  cudaFuncAttributeMaxDynamicSharedMemorySize, K1_SMEM);
    cudaFuncSetAttribute(k2_context, cudaFuncAttributeMaxDynamicSharedMemorySize, K2_SMEM);

    prep_enc<<<dim3(C_ / 32, S_ / 32, B_), 256>>>(encoded);
    prep_w<<<(LPAD * C_) / 256, 256>>>(W_attn);
    out_init<<<(B_ * L_ + 255) / 256, 256>>>(b_cls, out);
    k1_scores<<<dim3(NLT, B_), 512, K1_SMEM>>>();
    k2_context<<<dim3(NLT, 2, B_), 512, K2_SMEM>>>(W_cls, out);
}

// round 14
// speedup vs baseline: 1.3396x; 1.3396x over previous
#include <cuda_runtime.h>
#include <cuda_fp16.h>
#include <cstdint>

#define B_   8
#define C_   512
#define S_   2048
#define L_   8921
#define LPAD 8960
#define MT   64
#define NLT  (LPAD / MT)        // 140 label tiles

// ---------------- device scratch ----------------
__device__ __align__(16) __half g_encT[B_][S_][C_];   // [b][s][c]
__device__ __align__(16) __half g_wA[LPAD][C_];       // W_attn fp16
__device__ __align__(16) __half g_wC[LPAD][C_];       // W_cls  fp16

// ---------------- helpers ----------------
__device__ __forceinline__ uint32_t smem_u32(const void* p) {
    uint32_t a;
    asm("{ .reg .u64 t; cvta.to.shared.u64 t, %1; cvt.u32.u64 %0, t; }" : "=r"(a) : "l"(p));
    return a;
}
#define CPA(dst, src) \
    asm volatile("cp.async.cg.shared.global [%0], [%1], 16;" :: "r"(dst), "l"(src))
#define CPC() asm volatile("cp.async.commit_group;" ::: "memory")
#define CPW(n) asm volatile("cp.async.wait_group %0;" :: "n"(n) : "memory")

__device__ __forceinline__ void ldsm4(uint32_t* r, uint32_t addr) {
    asm volatile("ldmatrix.sync.aligned.m8n8.x4.shared.b16 {%0,%1,%2,%3}, [%4];"
        : "=r"(r[0]), "=r"(r[1]), "=r"(r[2]), "=r"(r[3]) : "r"(addr));
}
__device__ __forceinline__ void mma16816(float* d, const uint32_t* a, const uint32_t* b) {
    asm volatile("mma.sync.aligned.m16n8k16.row.col.f32.f16.f16.f32 "
        "{%0,%1,%2,%3}, {%4,%5,%6,%7}, {%8,%9}, {%0,%1,%2,%3};"
        : "+f"(d[0]), "+f"(d[1]), "+f"(d[2]), "+f"(d[3])
        : "r"(a[0]), "r"(a[1]), "r"(a[2]), "r"(a[3]), "r"(b[0]), "r"(b[1]));
}

// ---------------- prep kernels ----------------
__global__ void prep_enc(const float* __restrict__ enc) {
    __shared__ float t[32][33];
    int b = blockIdx.z, c0 = blockIdx.x * 32, s0 = blockIdx.y * 32;
    int tx = threadIdx.x & 31, ty = threadIdx.x >> 5;   // 256 threads: 32x8
    #pragma unroll
    for (int r = 0; r < 4; r++) {
        int c = c0 + ty + 8 * r;
        t[ty + 8 * r][tx] = enc[((size_t)b * C_ + c) * S_ + s0 + tx];
    }
    __syncthreads();
    #pragma unroll
    for (int r = 0; r < 4; r++) {
        int s = s0 + ty + 8 * r;
        g_encT[b][s][c0 + tx] = __float2half(t[tx][ty + 8 * r]);
    }
}
__global__ void prep_w(const float* __restrict__ Wa, const float* __restrict__ Wc) {
    int i = blockIdx.x * blockDim.x + threadIdx.x;      // over LPAD*C_
    int l = i >> 9, c = i & (C_ - 1);
    bool v = l < L_;
    g_wA[l][c] = __float2half(v ? Wa[(size_t)l * C_ + c] : 0.0f);
    g_wC[l][c] = __float2half(v ? Wc[(size_t)l * C_ + c] : 0.0f);
}

// ---------------- fused kernel: scores + exp + V + logits ----------------
// CTA: 64 labels x full S, batch b. 256 threads = 8 warps (2m x 4n), warp 32x64.
// Per s-chunk (256): GEMM over K=512 for BOTH A tiles (W_attn -> scores, W_cls -> V),
// then register-local epilogue: e = exp(score); Z += e; lg += e * V. No P scratch.
#define FK_A1    512
#define FK_A2    (512 + 65536)
#define FK_B     (512 + 2 * 65536)
#define FK_SMEM  (512 + 2 * 65536 + 2 * 32768)

__global__ __launch_bounds__(256, 1) void fused_attn(float* __restrict__ out,
                                                     const float* __restrict__ b_cls) {
    extern __shared__ char sm[];
    float* zs  = (float*)sm;          // [64]
    float* lgs = (float*)(sm + 256);  // [64]
    const uint32_t sA1u = smem_u32(sm + FK_A1);
    const uint32_t sA2u = smem_u32(sm + FK_A2);
    const uint32_t sBu  = smem_u32(sm + FK_B);
    const int tid = threadIdx.x, lane = tid & 31, wid = tid >> 5;
    const int wm = (wid >> 2) * 32, wn = (wid & 3) * 64;
    const int b = blockIdx.y, l0 = blockIdx.x * MT;

    if (tid < 64) { zs[tid] = 0.f; lgs[tid] = 0.f; }

    // stage A1 (W_attn) and A2 (W_cls): 64x512 -> 8 subtiles [64][64], 16B-XOR swizzled
    #pragma unroll
    for (int j = 0; j < 16; j++) {
        int lin = j * 256 + tid;                 // 4096 = 64 rows x 64 segs
        int row = lin >> 6, seg = lin & 63;
        int off = (seg >> 3) * 8192 + row * 128 + (((seg & 7) * 16) ^ ((row & 7) << 4));
        *(uint4*)(sm + FK_A1 + off) = *(const uint4*)&g_wA[l0 + row][seg * 8];
        *(uint4*)(sm + FK_A2 + off) = *(const uint4*)&g_wC[l0 + row][seg * 8];
    }
    __syncthreads();

    const int swz   = (lane & 7) << 4;
    const int arow  = lane & 15;                         // A: + wm + mt*16
    const int acolb = (lane >> 4) << 4;                  // A: + k0*2
    const int brow  = (lane & 7) + ((lane >> 4) << 3);   // B: + wn + ng*16
    const int bcolb = ((lane >> 3) & 1) << 4;            // B: + k0*2

    float sacc[2][8][4];   // scores
    float vacc[2][8][4];   // V = W_cls . enc
    float zr[2][2], lgr[2][2];
    #pragma unroll
    for (int mt = 0; mt < 2; mt++) {
        zr[mt][0] = zr[mt][1] = 0.f;
        lgr[mt][0] = lgr[mt][1] = 0.f;
    }

    // prologue: stage B chunk 0 (s-chunk 0, k-chunk 0): 256 rows x 64 cols fp16
    #pragma unroll
    for (int j = 0; j < 8; j++) {
        int lin = j * 256 + tid;
        int row = lin >> 3, c16 = lin & 7;
        CPA(sBu + row * 128 + ((c16 * 16) ^ ((row & 7) << 4)),
            (const char*)&g_encT[b][row][c16 * 8]);
    }
    CPC();

    #pragma unroll 1
    for (int it = 0; it < 64; it++) {                 // 8 s-chunks x 8 k-chunks
        const int kk = it & 7;
        const uint32_t bufo = (uint32_t)(it & 1) * 32768u;

        if (kk == 0) {
            #pragma unroll
            for (int mt = 0; mt < 2; mt++)
                #pragma unroll
                for (int nt = 0; nt < 8; nt++) {
                    sacc[mt][nt][0] = sacc[mt][nt][1] = sacc[mt][nt][2] = sacc[mt][nt][3] = 0.f;
                    vacc[mt][nt][0] = vacc[mt][nt][1] = vacc[mt][nt][2] = vacc[mt][nt][3] = 0.f;
                }
        }

        if (it < 63) {   // stage chunk it+1 into the other buffer
            const int n2 = (it + 1) >> 3, k2 = (it + 1) & 7;
            const uint32_t bo2 = (uint32_t)((it + 1) & 1) * 32768u;
            #pragma unroll
            for (int j = 0; j < 8; j++) {
                int lin = j * 256 + tid;
                int row = lin >> 3, c16 = lin & 7;
                CPA(sBu + bo2 + row * 128 + ((c16 * 16) ^ ((row & 7) << 4)),
                    (const char*)&g_encT[b][n2 * 256 + row][k2 * 64 + c16 * 8]);
            }
            CPC();
            CPW(1);
        } else {
            CPW(0);
        }
        __syncthreads();

        const uint32_t aB1 = sA1u + kk * 8192;
        const uint32_t aB2 = sA2u + kk * 8192;
        #pragma unroll
        for (int ks = 0; ks < 4; ks++) {
            const int k0b = ks * 32;
            uint32_t a1[2][4], a2[2][4], bfr[4][4];
            #pragma unroll
            for (int mt = 0; mt < 2; mt++) {
                const int aoff = (wm + mt * 16 + arow) * 128 + ((k0b + acolb) ^ swz);
                ldsm4(a1[mt], aB1 + aoff);
                ldsm4(a2[mt], aB2 + aoff);
            }
            #pragma unroll
            for (int ng = 0; ng < 4; ng++)
                ldsm4(bfr[ng], sBu + bufo + (wn + ng * 16 + brow) * 128 + ((k0b + bcolb) ^ swz));
            #pragma unroll
            for (int mt = 0; mt < 2; mt++)
                #pragma unroll
                for (int ng = 0; ng < 4; ng++) {
                    mma16816(sacc[mt][2 * ng],     a1[mt], &bfr[ng][0]);
                    mma16816(sacc[mt][2 * ng + 1], a1[mt], &bfr[ng][2]);
                    mma16816(vacc[mt][2 * ng],     a2[mt], &bfr[ng][0]);
                    mma16816(vacc[mt][2 * ng + 1], a2[mt], &bfr[ng][2]);
                }
        }
        __syncthreads();   // all warps done with this buffer before re-stage

        if (kk == 7) {     // register-local epilogue: e = exp(score); Z += e; lg += e*V
            #pragma unroll
            for (int mt = 0; mt < 2; mt++)
                #pragma unroll
                for (int nt = 0; nt < 8; nt++) {
                    float e0 = __expf(sacc[mt][nt][0]);
                    float e1 = __expf(sacc[mt][nt][1]);
                    float e2 = __expf(sacc[mt][nt][2]);
                    float e3 = __expf(sacc[mt][nt][3]);
                    zr[mt][0] += e0 + e1;
                    zr[mt][1] += e2 + e3;
                    lgr[mt][0] += e0 * vacc[mt][nt][0] + e1 * vacc[mt][nt][1];
                    lgr[mt][1] += e2 * vacc[mt][nt][2] + e3 * vacc[mt][nt][3];
                }
        }
    }

    // CTA reduce (each CTA covers the FULL s-range -> complete Z and logits)
    #pragma unroll
    for (int mt = 0; mt < 2; mt++) {
        const int lloc = wm + mt * 16 + (lane >> 2);
        atomicAdd(&zs[lloc],      zr[mt][0]);
        atomicAdd(&lgs[lloc],     lgr[mt][0]);
        atomicAdd(&zs[lloc + 8],  zr[mt][1]);
        atomicAdd(&lgs[lloc + 8], lgr[mt][1]);
    }
    __syncthreads();
    if (tid < 64) {
        const int gl = l0 + tid;
        if (gl < L_)
            out[(size_t)b * L_ + gl] = lgs[tid] / zs[tid] + b_cls[gl];
    }
}

// ---------------- launcher ----------------
extern "C" void kernel_launch(void* const* d_in, const int* in_sizes, int n_in,
                              void* d_out, int out_size) {
    const float* encoded = (const float*)d_in[0];
    const float* W_attn  = (const float*)d_in[1];
    // d_in[2] = b_attn: constant along the softmax axis -> no effect on output
    const float* W_cls   = (const float*)d_in[3];
    const float* b_cls   = (const float*)d_in[4];
    float* out = (float*)d_out;

    cudaFuncSetAttribute(fused_attn, cudaFuncAttributeMaxDynamicSharedMemorySize, FK_SMEM);

    prep_enc<<<dim3(C_ / 32, S_ / 32, B_), 256>>>(encoded);
    prep_w<<<(LPAD * C_) / 256, 256>>>(W_attn, W_cls);
    fused_attn<<<dim3(NLT, B_), 256, FK_SMEM>>>(out, b_cls);
}

// round 15
// speedup vs baseline: 1.3606x; 1.0157x over previous
#include <cuda_runtime.h>
#include <cuda_fp16.h>
#include <cstdint>

#define B_   8
#define C_   512
#define S_   2048
#define L_   8921
#define LPAD 8960
#define MT   64
#define NLT  (LPAD / MT)        // 140 label tiles

// ---------------- device scratch ----------------
__device__ __align__(16) __half g_encT[B_][S_][C_];   // [b][s][c]
__device__ __align__(16) __half g_wA[LPAD][C_];       // W_attn fp16
__device__ __align__(16) __half g_wC[LPAD][C_];       // W_cls  fp16

// ---------------- helpers ----------------
__device__ __forceinline__ uint32_t smem_u32(const void* p) {
    uint32_t a;
    asm("{ .reg .u64 t; cvta.to.shared.u64 t, %1; cvt.u32.u64 %0, t; }" : "=r"(a) : "l"(p));
    return a;
}
#define CPA(dst, src) \
    asm volatile("cp.async.cg.shared.global [%0], [%1], 16;" :: "r"(dst), "l"(src))
#define CPC() asm volatile("cp.async.commit_group;" ::: "memory")
#define CPW(n) asm volatile("cp.async.wait_group %0;" :: "n"(n) : "memory")

__device__ __forceinline__ void ldsm4(uint32_t* r, uint32_t addr) {
    asm volatile("ldmatrix.sync.aligned.m8n8.x4.shared.b16 {%0,%1,%2,%3}, [%4];"
        : "=r"(r[0]), "=r"(r[1]), "=r"(r[2]), "=r"(r[3]) : "r"(addr));
}
__device__ __forceinline__ void mma16816(float* d, const uint32_t* a, const uint32_t* b) {
    asm volatile("mma.sync.aligned.m16n8k16.row.col.f32.f16.f16.f32 "
        "{%0,%1,%2,%3}, {%4,%5,%6,%7}, {%8,%9}, {%0,%1,%2,%3};"
        : "+f"(d[0]), "+f"(d[1]), "+f"(d[2]), "+f"(d[3])
        : "r"(a[0]), "r"(a[1]), "r"(a[2]), "r"(a[3]), "r"(b[0]), "r"(b[1]));
}

// ---------------- prep kernels ----------------
__global__ void prep_enc(const float* __restrict__ enc) {
    __shared__ float t[32][33];
    int b = blockIdx.z, c0 = blockIdx.x * 32, s0 = blockIdx.y * 32;
    int tx = threadIdx.x & 31, ty = threadIdx.x >> 5;   // 256 threads: 32x8
    #pragma unroll
    for (int r = 0; r < 4; r++) {
        int c = c0 + ty + 8 * r;
        t[ty + 8 * r][tx] = enc[((size_t)b * C_ + c) * S_ + s0 + tx];
    }
    __syncthreads();
    #pragma unroll
    for (int r = 0; r < 4; r++) {
        int s = s0 + ty + 8 * r;
        g_encT[b][s][c0 + tx] = __float2half(t[tx][ty + 8 * r]);
    }
}
__global__ void prep_w(const float* __restrict__ Wa, const float* __restrict__ Wc) {
    int i = blockIdx.x * blockDim.x + threadIdx.x;      // over LPAD*C_
    int l = i >> 9, c = i & (C_ - 1);
    bool v = l < L_;
    g_wA[l][c] = __float2half(v ? Wa[(size_t)l * C_ + c] : 0.0f);
    g_wC[l][c] = __float2half(v ? Wc[(size_t)l * C_ + c] : 0.0f);
}

// ---------------- fused kernel: scores + exp + V + logits ----------------
// CTA: 64 labels x full S, batch b. 256 threads = 8 warps (2m x 4n), warp 32x64.
// Per s-chunk (256): GEMM over K=512 for BOTH A tiles (W_attn -> scores, W_cls -> V),
// register-local epilogue: e = exp(score); Z += e; lg += e * V. No P scratch.
// 3-stage B ring -> ONE barrier per iteration; ks loop software-pipelined.
#define FK_A1    512
#define FK_A2    (512 + 65536)
#define FK_B     (512 + 2 * 65536)
#define FK_SMEM  (512 + 2 * 65536 + 3 * 32768)

__global__ __launch_bounds__(256, 1) void fused_attn(float* __restrict__ out,
                                                     const float* __restrict__ b_cls) {
    extern __shared__ char sm[];
    float* zs  = (float*)sm;          // [64]
    float* lgs = (float*)(sm + 256);  // [64]
    const uint32_t sA1u = smem_u32(sm + FK_A1);
    const uint32_t sA2u = smem_u32(sm + FK_A2);
    const uint32_t sBu  = smem_u32(sm + FK_B);
    const int tid = threadIdx.x, lane = tid & 31, wid = tid >> 5;
    const int wm = (wid >> 2) * 32, wn = (wid & 3) * 64;
    const int b = blockIdx.y, l0 = blockIdx.x * MT;

    if (tid < 64) { zs[tid] = 0.f; lgs[tid] = 0.f; }

    // stage A1 (W_attn) and A2 (W_cls): 64x512 -> 8 subtiles [64][64], 16B-XOR swizzled
    #pragma unroll
    for (int j = 0; j < 16; j++) {
        int lin = j * 256 + tid;                 // 4096 = 64 rows x 64 segs
        int row = lin >> 6, seg = lin & 63;
        int off = (seg >> 3) * 8192 + row * 128 + (((seg & 7) * 16) ^ ((row & 7) << 4));
        *(uint4*)(sm + FK_A1 + off) = *(const uint4*)&g_wA[l0 + row][seg * 8];
        *(uint4*)(sm + FK_A2 + off) = *(const uint4*)&g_wC[l0 + row][seg * 8];
    }
    __syncthreads();

    const int swz   = (lane & 7) << 4;
    const int arow  = lane & 15;                         // A: + wm + mt*16
    const int acolb = (lane >> 4) << 4;                  // A: + k0*2
    const int brow  = (lane & 7) + ((lane >> 4) << 3);   // B: + wn + ng*16
    const int bcolb = ((lane >> 3) & 1) << 4;            // B: + k0*2

    float sacc[2][8][4];   // scores
    float vacc[2][8][4];   // V = W_cls . enc
    float zr[2][2], lgr[2][2];
    #pragma unroll
    for (int mt = 0; mt < 2; mt++) {
        zr[mt][0] = zr[mt][1] = 0.f;
        lgr[mt][0] = lgr[mt][1] = 0.f;
    }

    // prologue: stage B chunk 0 into ring slot 0 (256 rows x 64 cols fp16)
    #pragma unroll
    for (int j = 0; j < 8; j++) {
        int lin = j * 256 + tid;
        int row = lin >> 3, c16 = lin & 7;
        CPA(sBu + row * 128 + ((c16 * 16) ^ ((row & 7) << 4)),
            (const char*)&g_encT[b][row][c16 * 8]);
    }
    CPC();

    #pragma unroll 1
    for (int it = 0; it < 64; it++) {                 // 8 s-chunks x 8 k-chunks
        const int kk = it & 7;
        const uint32_t bufo = (uint32_t)(it % 3) * 32768u;

        if (kk == 0) {
            #pragma unroll
            for (int mt = 0; mt < 2; mt++)
                #pragma unroll
                for (int nt = 0; nt < 8; nt++) {
                    sacc[mt][nt][0] = sacc[mt][nt][1] = sacc[mt][nt][2] = sacc[mt][nt][3] = 0.f;
                    vacc[mt][nt][0] = vacc[mt][nt][1] = vacc[mt][nt][2] = vacc[mt][nt][3] = 0.f;
                }
        }

        if (it < 63) {   // stage chunk it+1 into ring slot (it+1)%3
            const int n2 = (it + 1) >> 3, k2 = (it + 1) & 7;
            const uint32_t bo2 = (uint32_t)((it + 1) % 3) * 32768u;
            #pragma unroll
            for (int j = 0; j < 8; j++) {
                int lin = j * 256 + tid;
                int row = lin >> 3, c16 = lin & 7;
                CPA(sBu + bo2 + row * 128 + ((c16 * 16) ^ ((row & 7) << 4)),
                    (const char*)&g_encT[b][n2 * 256 + row][k2 * 64 + c16 * 8]);
            }
            CPC();
            CPW(1);
        } else {
            CPW(0);
        }
        __syncthreads();   // single barrier: ring slot (it+1)%3 last read at it-2, fenced by it-1's barrier

        const uint32_t aB1 = sA1u + kk * 8192;
        const uint32_t aB2 = sA2u + kk * 8192;

        // -------- software-pipelined ks loop: load ks+1 frags during ks MMAs --------
        uint32_t a1[2][2][4], a2[2][2][4], bfr[2][4][4];
        {   // preload ks = 0 into slot 0
            #pragma unroll
            for (int mt = 0; mt < 2; mt++) {
                const int aoff = (wm + mt * 16 + arow) * 128 + (acolb ^ swz);
                ldsm4(a1[0][mt], aB1 + aoff);
                ldsm4(a2[0][mt], aB2 + aoff);
            }
            #pragma unroll
            for (int ng = 0; ng < 4; ng++)
                ldsm4(bfr[0][ng], sBu + bufo + (wn + ng * 16 + brow) * 128 + (bcolb ^ swz));
        }
        #pragma unroll
        for (int ks = 0; ks < 4; ks++) {
            const int cur = ks & 1, nxt = cur ^ 1;
            if (ks < 3) {
                const int k1b = (ks + 1) * 32;
                #pragma unroll
                for (int mt = 0; mt < 2; mt++) {
                    const int aoff = (wm + mt * 16 + arow) * 128 + ((k1b + acolb) ^ swz);
                    ldsm4(a1[nxt][mt], aB1 + aoff);
                    ldsm4(a2[nxt][mt], aB2 + aoff);
                }
                #pragma unroll
                for (int ng = 0; ng < 4; ng++)
                    ldsm4(bfr[nxt][ng],
                          sBu + bufo + (wn + ng * 16 + brow) * 128 + ((k1b + bcolb) ^ swz));
            }
            #pragma unroll
            for (int mt = 0; mt < 2; mt++)
                #pragma unroll
                for (int ng = 0; ng < 4; ng++) {
                    mma16816(sacc[mt][2 * ng],     a1[cur][mt], &bfr[cur][ng][0]);
                    mma16816(sacc[mt][2 * ng + 1], a1[cur][mt], &bfr[cur][ng][2]);
                    mma16816(vacc[mt][2 * ng],     a2[cur][mt], &bfr[cur][ng][0]);
                    mma16816(vacc[mt][2 * ng + 1], a2[cur][mt], &bfr[cur][ng][2]);
                }
        }

        if (kk == 7) {     // register-local epilogue: e = exp(score); Z += e; lg += e*V
            #pragma unroll
            for (int mt = 0; mt < 2; mt++)
                #pragma unroll
                for (int nt = 0; nt < 8; nt++) {
                    float e0 = __expf(sacc[mt][nt][0]);
                    float e1 = __expf(sacc[mt][nt][1]);
                    float e2 = __expf(sacc[mt][nt][2]);
                    float e3 = __expf(sacc[mt][nt][3]);
                    zr[mt][0] += e0 + e1;
                    zr[mt][1] += e2 + e3;
                    lgr[mt][0] += e0 * vacc[mt][nt][0] + e1 * vacc[mt][nt][1];
                    lgr[mt][1] += e2 * vacc[mt][nt][2] + e3 * vacc[mt][nt][3];
                }
        }
    }

    // CTA reduce (each CTA covers the FULL s-range -> complete Z and logits)
    #pragma unroll
    for (int mt = 0; mt < 2; mt++) {
        const int lloc = wm + mt * 16 + (lane >> 2);
        atomicAdd(&zs[lloc],      zr[mt][0]);
        atomicAdd(&lgs[lloc],     lgr[mt][0]);
        atomicAdd(&zs[lloc + 8],  zr[mt][1]);
        atomicAdd(&lgs[lloc + 8], lgr[mt][1]);
    }
    __syncthreads();
    if (tid < 64) {
        const int gl = l0 + tid;
        if (gl < L_)
            out[(size_t)b * L_ + gl] = lgs[tid] / zs[tid] + b_cls[gl];
    }
}

// ---------------- launcher ----------------
extern "C" void kernel_launch(void* const* d_in, const int* in_sizes, int n_in,
                              void* d_out, int out_size) {
    const float* encoded = (const float*)d_in[0];
    const float* W_attn  = (const float*)d_in[1];
    // d_in[2] = b_attn: constant along the softmax axis -> no effect on output
    const float* W_cls   = (const float*)d_in[3];
    const float* b_cls   = (const float*)d_in[4];
    float* out = (float*)d_out;

    cudaFuncSetAttribute(fused_attn, cudaFuncAttributeMaxDynamicSharedMemorySize, FK_SMEM);

    prep_enc<<<dim3(C_ / 32, S_ / 32, B_), 256>>>(encoded);
    prep_w<<<(LPAD * C_) / 256, 256>>>(W_attn, W_cls);
    fused_attn<<<dim3(NLT, B_), 256, FK_SMEM>>>(out, b_cls);
}

// round 17
// speedup vs baseline: 1.3750x; 1.0105x over previous
#include <cuda_runtime.h>
#include <cuda_fp16.h>
#include <cstdint>

#define B_   8
#define C_   512
#define S_   2048
#define L_   8921
#define LPAD 8960
#define MT   64
#define NLT  (LPAD / MT)        // 140 label tiles
#define LOG2E 1.4426950408889634f

// ---------------- device scratch ----------------
__device__ __align__(16) __half g_encT[B_][S_][C_];   // [b][s][c]
__device__ __align__(16) __half g_wA[LPAD][C_];       // W_attn fp16
__device__ __align__(16) __half g_wC[LPAD][C_];       // W_cls  fp16

// ---------------- helpers ----------------
__device__ __forceinline__ uint32_t smem_u32(const void* p) {
    uint32_t a;
    asm("{ .reg .u64 t; cvta.to.shared.u64 t, %1; cvt.u32.u64 %0, t; }" : "=r"(a) : "l"(p));
    return a;
}
#define CPA(dst, src) \
    asm volatile("cp.async.cg.shared.global [%0], [%1], 16;" :: "r"(dst), "l"(src))
#define CPC() asm volatile("cp.async.commit_group;" ::: "memory")
#define CPW(n) asm volatile("cp.async.wait_group %0;" :: "n"(n) : "memory")

__device__ __forceinline__ void ldsm4(uint32_t* r, uint32_t addr) {
    asm volatile("ldmatrix.sync.aligned.m8n8.x4.shared.b16 {%0,%1,%2,%3}, [%4];"
        : "=r"(r[0]), "=r"(r[1]), "=r"(r[2]), "=r"(r[3]) : "r"(addr));
}
__device__ __forceinline__ void mma16816(float* d, const uint32_t* a, const uint32_t* b) {
    asm volatile("mma.sync.aligned.m16n8k16.row.col.f32.f16.f16.f32 "
        "{%0,%1,%2,%3}, {%4,%5,%6,%7}, {%8,%9}, {%0,%1,%2,%3};"
        : "+f"(d[0]), "+f"(d[1]), "+f"(d[2]), "+f"(d[3])
        : "r"(a[0]), "r"(a[1]), "r"(a[2]), "r"(a[3]), "r"(b[0]), "r"(b[1]));
}
__device__ __forceinline__ uint32_t ex2_f16x2(uint32_t x) {
    uint32_t r;
    asm("ex2.approx.f16x2 %0, %1;" : "=r"(r) : "r"(x));
    return r;
}

// ---------------- prep kernels ----------------
__global__ void prep_enc(const float* __restrict__ enc) {
    __shared__ float t[32][33];
    int b = blockIdx.z, c0 = blockIdx.x * 32, s0 = blockIdx.y * 32;
    int tx = threadIdx.x & 31, ty = threadIdx.x >> 5;   // 256 threads: 32x8
    #pragma unroll
    for (int r = 0; r < 4; r++) {
        int c = c0 + ty + 8 * r;
        t[ty + 8 * r][tx] = enc[((size_t)b * C_ + c) * S_ + s0 + tx];
    }
    __syncthreads();
    #pragma unroll
    for (int r = 0; r < 4; r++) {
        int s = s0 + ty + 8 * r;
        g_encT[b][s][c0 + tx] = __float2half(t[tx][ty + 8 * r]);
    }
}
__global__ void prep_w(const float* __restrict__ Wa, const float* __restrict__ Wc) {
    int i = blockIdx.x * blockDim.x + threadIdx.x;      // over LPAD*C_
    int l = i >> 9, c = i & (C_ - 1);
    bool v = l < L_;
    g_wA[l][c] = __float2half(v ? Wa[(size_t)l * C_ + c] : 0.0f);
    g_wC[l][c] = __float2half(v ? Wc[(size_t)l * C_ + c] : 0.0f);
}

// ---------------- fused kernel: scores + exp + V + logits ----------------
// CTA: 64 labels x full S, batch b. 256 threads = 8 warps (2m x 4n), warp 32x64.
// 32 iterations: 8 s-chunks (256) x 4 k-chunks (128); 256 MMAs/warp per iteration.
// A-slices (both W tiles, current k-chunk) + B chunk each in a 2-slot ring with
// TWO barriers per iteration: barrier A (overwrite safety) -> stage -> CPW ->
// barrier B (cp.async visibility) -> MMA. Epilogue uses ex2.approx.f16x2.
#define FK_AR    512                       // A ring: 2 x 32768 (wA 16K + wC 16K per slot)
#define FK_BR    (512 + 2 * 32768)         // B ring: 2 x 65536
#define FK_SMEM  (512 + 2 * 32768 + 2 * 65536)   // 197,120

__global__ __launch_bounds__(256, 1) void fused_attn(float* __restrict__ out,
                                                     const float* __restrict__ b_cls) {
    extern __shared__ char sm[];
    float* zs  = (float*)sm;          // [64]
    float* lgs = (float*)(sm + 256);  // [64]
    const uint32_t sAr = smem_u32(sm + FK_AR);
    const uint32_t sBr = smem_u32(sm + FK_BR);
    const int tid = threadIdx.x, lane = tid & 31, wid = tid >> 5;
    const int wm = (wid >> 2) * 32, wn = (wid & 3) * 64;
    const int b = blockIdx.y, l0 = blockIdx.x * MT;

    if (tid < 64) { zs[tid] = 0.f; lgs[tid] = 0.f; }

    const int swz   = (lane & 7) << 4;
    const int arow  = lane & 15;                         // A: + wm + mt*16
    const int acolb = (lane >> 4) << 4;                  // A: + k0*2
    const int brow  = (lane & 7) + ((lane >> 4) << 3);   // B: + wn + ng*16
    const int bcolb = ((lane >> 3) & 1) << 4;            // B: + k0*2

    float sacc[2][8][4];   // scores
    float vacc[2][8][4];   // V = W_cls . enc
    float zr[2][2], lgr[2][2];
    #pragma unroll
    for (int mt = 0; mt < 2; mt++) {
        zr[mt][0] = zr[mt][1] = 0.f;
        lgr[mt][0] = lgr[mt][1] = 0.f;
    }

    // ---- prologue: stage chunk 0 (A slices kc=0 + B chunk s0=0,kc=0) into slot 0 ----
    #pragma unroll
    for (int j = 0; j < 8; j++) {               // A: 2048 x 16B (2 tiles of 64x128)
        int lin = tid + j * 256;
        int row = (lin >> 4) & 63, seg = lin & 15;
        int off = ((j >= 4) ? 16384 : 0) + (seg >> 3) * 8192 + row * 128 +
                  (((seg & 7) * 16) ^ ((row & 7) << 4));
        const __half* src = (j < 4) ? &g_wA[l0 + row][seg * 8]
                                    : &g_wC[l0 + row][seg * 8];
        CPA(sAr + off, (const char*)src);
    }
    #pragma unroll
    for (int j = 0; j < 16; j++) {              // B: 4096 x 16B (256 s x 128 k)
        int lin = tid + j * 256;
        int row = lin >> 4, seg = lin & 15;
        int off = (seg >> 3) * 32768 + row * 128 + (((seg & 7) * 16) ^ ((row & 7) << 4));
        CPA(sBr + off, (const char*)&g_encT[b][row][seg * 8]);
    }
    CPC();

    #pragma unroll 1
    for (int it = 0; it < 32; it++) {           // 8 s-chunks x 4 k-chunks
        const int kc = it & 3;
        const uint32_t abuf = (uint32_t)(it & 1) * 32768u;
        const uint32_t bbuf = (uint32_t)(it & 1) * 65536u;

        __syncthreads();   // barrier A: prior iteration's reads done -> safe to overwrite other slot

        if (kc == 0) {
            #pragma unroll
            for (int mt = 0; mt < 2; mt++)
                #pragma unroll
                for (int nt = 0; nt < 8; nt++) {
                    sacc[mt][nt][0] = sacc[mt][nt][1] = sacc[mt][nt][2] = sacc[mt][nt][3] = 0.f;
                    vacc[mt][nt][0] = vacc[mt][nt][1] = vacc[mt][nt][2] = vacc[mt][nt][3] = 0.f;
                }
        }

        if (it < 31) {   // stage chunk it+1 into the other slot
            const int n2 = (it + 1) >> 2, k2 = (it + 1) & 3;
            const uint32_t aS = sAr + ((uint32_t)((it + 1) & 1) * 32768u);
            const uint32_t bS = sBr + ((uint32_t)((it + 1) & 1) * 65536u);
            #pragma unroll
            for (int j = 0; j < 8; j++) {
                int lin = tid + j * 256;
                int row = (lin >> 4) & 63, seg = lin & 15;
                int off = ((j >= 4) ? 16384 : 0) + (seg >> 3) * 8192 + row * 128 +
                          (((seg & 7) * 16) ^ ((row & 7) << 4));
                const __half* src = (j < 4) ? &g_wA[l0 + row][k2 * 128 + seg * 8]
                                            : &g_wC[l0 + row][k2 * 128 + seg * 8];
                CPA(aS + off, (const char*)src);
            }
            #pragma unroll
            for (int j = 0; j < 16; j++) {
                int lin = tid + j * 256;
                int row = lin >> 4, seg = lin & 15;
                int off = (seg >> 3) * 32768 + row * 128 + (((seg & 7) * 16) ^ ((row & 7) << 4));
                CPA(bS + off, (const char*)&g_encT[b][n2 * 256 + row][k2 * 128 + seg * 8]);
            }
            CPC();
            CPW(1);      // own copies of chunk `it` complete
        } else {
            CPW(0);
        }
        __syncthreads();   // barrier B: ALL threads' chunk-`it` copies visible

        // -------- software-pipelined ks loop (8 steps of k16) --------
        uint32_t a1[2][2][4], a2[2][2][4], bfr[2][4][4];
        {   // preload ks = 0
            const uint32_t aB1 = sAr + abuf, aB2 = aB1 + 16384;
            #pragma unroll
            for (int mt = 0; mt < 2; mt++) {
                const int aoff = (wm + mt * 16 + arow) * 128 + (acolb ^ swz);
                ldsm4(a1[0][mt], aB1 + aoff);
                ldsm4(a2[0][mt], aB2 + aoff);
            }
            #pragma unroll
            for (int ng = 0; ng < 4; ng++)
                ldsm4(bfr[0][ng], sBr + bbuf + (wn + ng * 16 + brow) * 128 + (bcolb ^ swz));
        }
        #pragma unroll
        for (int ks = 0; ks < 8; ks++) {
            const int cur = ks & 1, nxt = cur ^ 1;
            if (ks < 7) {
                const int k1 = ks + 1;
                const int k1b = (k1 & 3) * 32;
                const uint32_t aB1 = sAr + abuf + (k1 >> 2) * 8192, aB2 = aB1 + 16384;
                const uint32_t bB  = sBr + bbuf + (k1 >> 2) * 32768;
                #pragma unroll
                for (int mt = 0; mt < 2; mt++) {
                    const int aoff = (wm + mt * 16 + arow) * 128 + ((k1b + acolb) ^ swz);
                    ldsm4(a1[nxt][mt], aB1 + aoff);
                    ldsm4(a2[nxt][mt], aB2 + aoff);
                }
                #pragma unroll
                for (int ng = 0; ng < 4; ng++)
                    ldsm4(bfr[nxt][ng],
                          bB + (wn + ng * 16 + brow) * 128 + ((k1b + bcolb) ^ swz));
            }
            #pragma unroll
            for (int mt = 0; mt < 2; mt++)
                #pragma unroll
                for (int ng = 0; ng < 4; ng++) {
                    mma16816(sacc[mt][2 * ng],     a1[cur][mt], &bfr[cur][ng][0]);
                    mma16816(sacc[mt][2 * ng + 1], a1[cur][mt], &bfr[cur][ng][2]);
                    mma16816(vacc[mt][2 * ng],     a2[cur][mt], &bfr[cur][ng][0]);
                    mma16816(vacc[mt][2 * ng + 1], a2[cur][mt], &bfr[cur][ng][2]);
                }
        }

        if (kc == 3) {     // epilogue: e = 2^(score*log2e) via ex2.f16x2; Z += e; lg += e*V
            #pragma unroll
            for (int mt = 0; mt < 2; mt++)
                #pragma unroll
                for (int nt = 0; nt < 8; nt++) {
                    __half2 h01 = __floats2half2_rn(sacc[mt][nt][0] * LOG2E,
                                                    sacc[mt][nt][1] * LOG2E);
                    __half2 h23 = __floats2half2_rn(sacc[mt][nt][2] * LOG2E,
                                                    sacc[mt][nt][3] * LOG2E);
                    uint32_t e01u = ex2_f16x2(*(uint32_t*)&h01);
                    uint32_t e23u = ex2_f16x2(*(uint32_t*)&h23);
                    float2 e01 = __half22float2(*(__half2*)&e01u);
                    float2 e23 = __half22float2(*(__half2*)&e23u);
                    zr[mt][0] += e01.x + e01.y;
                    zr[mt][1] += e23.x + e23.y;
                    lgr[mt][0] += e01.x * vacc[mt][nt][0] + e01.y * vacc[mt][nt][1];
                    lgr[mt][1] += e23.x * vacc[mt][nt][2] + e23.y * vacc[mt][nt][3];
                }
        }
    }

    // CTA reduce (each CTA covers the FULL s-range -> complete Z and logits)
    #pragma unroll
    for (int mt = 0; mt < 2; mt++) {
        const int lloc = wm + mt * 16 + (lane >> 2);
        atomicAdd(&zs[lloc],      zr[mt][0]);
        atomicAdd(&lgs[lloc],     lgr[mt][0]);
        atomicAdd(&zs[lloc + 8],  zr[mt][1]);
        atomicAdd(&lgs[lloc + 8], lgr[mt][1]);
    }
    __syncthreads();
    if (tid < 64) {
        const int gl = l0 + tid;
        if (gl < L_)
            out[(size_t)b * L_ + gl] = lgs[tid] / zs[tid] + b_cls[gl];
    }
}

// ---------------- launcher ----------------
extern "C" void kernel_launch(void* const* d_in, const int* in_sizes, int n_in,
                              void* d_out, int out_size) {
    const float* encoded = (const float*)d_in[0];
    const float* W_attn  = (const float*)d_in[1];
    // d_in[2] = b_attn: constant along the softmax axis -> no effect on output
    const float* W_cls   = (const float*)d_in[3];
    const float* b_cls   = (const float*)d_in[4];
    float* out = (float*)d_out;

    cudaFuncSetAttribute(fused_attn, cudaFuncAttributeMaxDynamicSharedMemorySize, FK_SMEM);

    prep_enc<<<dim3(C_ / 32, S_ / 32, B_), 256>>>(encoded);
    prep_w<<<(LPAD * C_) / 256, 256>>>(W_attn, W_cls);
    fused_attn<<<dim3(NLT, B_), 256, FK_SMEM>>>(out, b_cls);
}